// round 15
// baseline (speedup 1.0000x reference)
#include <cuda_runtime.h>
#include <cuda_bf16.h>
#include <cstdint>

// Problem: B=4, Lp=Lq=256, D=256, H=256.
// Inputs: Hp, Hq, Wc1, Wc2, vc, Wb, Wd, vd, Wm, vm (all fp32)
// Output: concat(qc, qb, qd, qm), each (B, Lp, D) fp32.

#define BB 4
#define LL 256
#define DD 256
#define HH 256

// -------- scratch (static device globals; no allocation allowed) --------
__device__ float g_S1[BB * LL * HH];
__device__ float g_S2[BB * LL * HH];
__device__ float g_G [BB * LL * HH];
__device__ float g_M1[BB * LL * HH];
__device__ float g_M2[BB * LL * HH];
__device__ float g_SD0[BB * LL * LL];   // branch-d partial (h 0..127)
__device__ float g_SD1[BB * LL * LL];   // branch-d partial (h 128..255)
__device__ float g_SC[BB * LL * LL];
__device__ float g_SB[BB * LL * LL];
__device__ float g_SM[BB * LL * LL];
__device__ uint32_t g_Wd32[HH * DD];      // Wd^T in tf32 bits [h][k]
__device__ uint32_t g_WT32[3][DD * HH];   // {Wc1,Wc2,Wm}^T in tf32 bits [n][k]

// ======================= helpers =======================
__device__ __forceinline__ uint32_t smem_u32(const void* p) {
    uint32_t a;
    asm("{ .reg .u64 t; cvta.to.shared.u64 t, %1; cvt.u32.u64 %0, t; }"
        : "=r"(a) : "l"(p));
    return a;
}

__device__ __forceinline__ float tanh_fast(float x) {
    float y;
    asm("tanh.approx.f32 %0, %1;" : "=f"(y) : "f"(x));
    return y;
}

__device__ __forceinline__ uint32_t tf32_of(float f) {
    uint32_t u;
    asm("cvt.rna.tf32.f32 %0, %1;" : "=r"(u) : "f"(f));
    return u;
}

#define SWZ128(off) ((off) ^ (((off) >> 3) & 0x70))

#define CP_ASYNC16(dst_u32, src_ptr) \
    asm volatile("cp.async.cg.shared.global [%0], [%1], 16;" \
                 :: "r"(dst_u32), "l"(src_ptr) : "memory")
#define CP_COMMIT() asm volatile("cp.async.commit_group;" ::: "memory")
#define CP_WAIT0()  asm volatile("cp.async.wait_group 0;" ::: "memory")
#define CP_WAIT1()  asm volatile("cp.async.wait_group 1;" ::: "memory")

__device__ __forceinline__ void ldm_x4(uint32_t* r, uint32_t addr) {
    asm volatile("ldmatrix.sync.aligned.m8n8.x4.shared.b16 {%0,%1,%2,%3}, [%4];"
                 : "=r"(r[0]), "=r"(r[1]), "=r"(r[2]), "=r"(r[3]) : "r"(addr));
}

__device__ __forceinline__ void ldm_x2(uint32_t* r, uint32_t addr) {
    asm volatile("ldmatrix.sync.aligned.m8n8.x2.shared.b16 {%0,%1}, [%2];"
                 : "=r"(r[0]), "=r"(r[1]) : "r"(addr));
}

__device__ __forceinline__ void mma_tf32(float* d, const uint32_t* a, const uint32_t* b) {
    asm volatile(
        "mma.sync.aligned.m16n8k8.row.col.f32.tf32.tf32.f32 "
        "{%0,%1,%2,%3}, {%4,%5,%6,%7}, {%8,%9}, {%0,%1,%2,%3};"
        : "+f"(d[0]), "+f"(d[1]), "+f"(d[2]), "+f"(d[3])
        : "r"(a[0]), "r"(a[1]), "r"(a[2]), "r"(a[3]), "r"(b[0]), "r"(b[1]));
}

// ======================= kernel 0: weight transposes -> tf32 =======================
__global__ void prep_w_kernel(const float* __restrict__ Wc1, const float* __restrict__ Wc2,
                              const float* __restrict__ Wm,  const float* __restrict__ Wd) {
    int k = blockIdx.x, n = threadIdx.x, w = blockIdx.y;
    const float* src = (w == 0) ? Wc1 : (w == 1) ? Wc2 : (w == 2) ? Wm : Wd;
    uint32_t v = tf32_of(src[k * 256 + n]);
    if (w < 3) g_WT32[w][n * 256 + k] = v;
    else       g_Wd32[n * 256 + k] = v;
}

// ======================= kernel 1a: 4 tanh-gated projections via tf32 mma =======================
static constexpr int PBUF = 24576;   // A 8KB + B 16KB
static constexpr int SMEM_P = 2 * PBUF;  // 48KB

__global__ __launch_bounds__(256)
void projmma_kernel(const float* __restrict__ Hp, const float* __restrict__ Hq) {
    extern __shared__ char psm[];
    const uint32_t sb = smem_u32(psm);
    const int bx = blockIdx.x;
    const int gemm = bx >> 5;
    const int rr = bx & 31;
    const int mb = (rr >> 1) * 64, nb = (rr & 1) * 128;
    const float* A = (gemm == 1 || gemm == 3) ? Hp : Hq;
    const uint32_t* WT = g_WT32[gemm < 2 ? gemm : 2];
    float* C = (gemm == 0) ? g_S1 : (gemm == 1) ? g_S2 : (gemm == 2) ? g_M1 : g_M2;

    const int tid = threadIdx.x, lane = tid & 31, warp = tid >> 5;
    const int wm = warp >> 1, wn = warp & 1;

    const int a_row  = wm * 16 + (lane & 15);
    const int a_cb   = (lane >> 4) * 16;
    const int b_row2 = wn * 64 + ((lane >> 4) & 1) * 8 + (lane & 7);
    const int b_cb2  = ((lane >> 3) & 1) * 16;

    float acc[8][4];
    #pragma unroll
    for (int n = 0; n < 8; ++n)
        #pragma unroll
        for (int e = 0; e < 4; ++e) acc[n][e] = 0.f;

    auto fillA = [&](char* base, int kc) {
        #pragma unroll
        for (int t = 0; t < 2; ++t) {
            int i = tid + t * 256;
            int row = i >> 3, c = i & 7;
            float4 v = *reinterpret_cast<const float4*>(
                &A[(mb + row) * 256 + kc * 32 + c * 4]);
            uint4 u;
            u.x = tf32_of(v.x); u.y = tf32_of(v.y);
            u.z = tf32_of(v.z); u.w = tf32_of(v.w);
            *reinterpret_cast<uint4*>(base + SWZ128((uint32_t)(row * 128 + c * 16))) = u;
        }
    };
    auto fillB = [&](char* base, int kc) {
        uint32_t bB = smem_u32(base + 8192);
        #pragma unroll
        for (int t = 0; t < 4; ++t) {
            int i = tid + t * 256;
            int row = i >> 3, c = i & 7;
            CP_ASYNC16(bB + SWZ128((uint32_t)(row * 128 + c * 16)),
                       (const void*)&WT[(nb + row) * 256 + kc * 32 + c * 4]);
        }
        CP_COMMIT();
    };

    fillA(psm, 0);
    fillB(psm, 0);
    CP_WAIT0();
    __syncthreads();

    for (int kc = 0; kc < 8; ++kc) {
        char* nxt = psm + ((kc + 1) & 1) * PBUF;
        const uint32_t aA = sb + (uint32_t)(kc & 1) * PBUF;
        const uint32_t aB = aA + 8192;

        if (kc < 7) fillB(nxt, kc + 1);

        #pragma unroll
        for (int ks = 0; ks < 4; ++ks) {
            const int k0b = ks * 32;
            uint32_t a[4];
            ldm_x4(a, aA + SWZ128((uint32_t)(a_row * 128 + k0b + a_cb)));
            #pragma unroll
            for (int n2 = 0; n2 < 4; ++n2) {
                uint32_t bf[4];
                ldm_x4(bf, aB + SWZ128((uint32_t)((b_row2 + n2 * 16) * 128 + k0b + b_cb2)));
                mma_tf32(acc[2 * n2],     a, bf);
                mma_tf32(acc[2 * n2 + 1], a, bf + 2);
            }
        }

        if (kc < 7) { fillA(nxt, kc + 1); CP_WAIT0(); }
        __syncthreads();
    }

    const int r0 = mb + wm * 16 + (lane >> 2);
    #pragma unroll
    for (int n2 = 0; n2 < 4; ++n2)
        #pragma unroll
        for (int half = 0; half < 2; ++half) {
            int cb = nb + wn * 64 + n2 * 16 + half * 8 + (lane & 3) * 2;
            const float* a4 = acc[2 * n2 + half];
            C[r0 * 256 + cb]           = a4[0];
            C[r0 * 256 + cb + 1]       = a4[1];
            C[(r0 + 8) * 256 + cb]     = a4[2];
            C[(r0 + 8) * 256 + cb + 1] = a4[3];
        }
}

// ======================= kernel 1b: G = Hq @ Wb in fp32 =======================
__global__ void projb_kernel(const float* __restrict__ Hq, const float* __restrict__ Wb) {
    const int mb = blockIdx.x * 64, nb = blockIdx.y * 64;
    const int tid = threadIdx.x, ty = tid >> 4, tx = tid & 15;

    __shared__ float As[16][68];
    __shared__ float Bs[16][68];

    float acc[4][4] = {};
    for (int kt = 0; kt < 16; ++kt) {
        {
            int m = tid >> 2, k4 = (tid & 3) * 4;
            float4 v = *reinterpret_cast<const float4*>(&Hq[(mb + m) * 256 + kt * 16 + k4]);
            As[k4 + 0][m] = v.x; As[k4 + 1][m] = v.y;
            As[k4 + 2][m] = v.z; As[k4 + 3][m] = v.w;
        }
        {
            int k = tid >> 4, n4 = (tid & 15) * 4;
            float4 v = *reinterpret_cast<const float4*>(&Wb[(kt * 16 + k) * 256 + nb + n4]);
            *reinterpret_cast<float4*>(&Bs[k][n4]) = v;
        }
        __syncthreads();
        #pragma unroll
        for (int k = 0; k < 16; ++k) {
            float a[4], bv[4];
            #pragma unroll
            for (int i = 0; i < 4; ++i) a[i] = As[k][ty + 16 * i];
            #pragma unroll
            for (int j = 0; j < 4; ++j) bv[j] = Bs[k][tx + 16 * j];
            #pragma unroll
            for (int i = 0; i < 4; ++i)
                #pragma unroll
                for (int j = 0; j < 4; ++j) acc[i][j] = fmaf(a[i], bv[j], acc[i][j]);
        }
        __syncthreads();
    }
    #pragma unroll
    for (int i = 0; i < 4; ++i)
        #pragma unroll
        for (int j = 0; j < 4; ++j)
            g_G[(mb + ty + 16 * i) * 256 + nb + tx + 16 * j] = acc[i][j];
}

// ======================= kernel 2: branch d — 128q x 128h CTAs, 2 CTAs/SM =======================
// grid (4, LL, BB): blockIdx.x = qh*2+hh. 256 threads, 8 warps = wq(0..1) x wh(0..3),
// warp tile 64q x 32h, acc[4][4][4] = 64 regs. K in 8 chunks of 32, r8 LDG-prefetch pipeline.
static constexpr int BUFSZ   = 32768;             // A 16KB + B 16KB
static constexpr int OFF_HP  = 2 * BUFSZ;         // 65536
static constexpr int OFF_VD  = OFF_HP + 1024;
static constexpr int OFF_SDP = OFF_VD + 1024;
static constexpr int SMEM_D  = OFF_SDP + 1024;    // 68608 -> 2 CTAs/SM fits 228KB

__device__ __forceinline__ void ldA_regs(float4 (&pf)[4], const float* __restrict__ hq_b,
                                         int qh, int kc, int tid) {
    #pragma unroll
    for (int t = 0; t < 4; ++t) {
        int i = tid + t * 256;            // 0..1023 (128 rows x 8 chunks)
        int row = i >> 3, c = i & 7;
        pf[t] = *reinterpret_cast<const float4*>(
            &hq_b[(qh * 128 + row) * DD + kc * 32 + c * 4]);
    }
}

__device__ __forceinline__ void stA_regs(char* base, const float4 (&pf)[4],
                                         const float* hp_s, int kc, int tid) {
    #pragma unroll
    for (int t = 0; t < 4; ++t) {
        int i = tid + t * 256;
        int row = i >> 3, c = i & 7;
        int kg = kc * 32 + c * 4;
        uint4 r;
        r.x = tf32_of(pf[t].x * hp_s[kg + 0]);
        r.y = tf32_of(pf[t].y * hp_s[kg + 1]);
        r.z = tf32_of(pf[t].z * hp_s[kg + 2]);
        r.w = tf32_of(pf[t].w * hp_s[kg + 3]);
        *reinterpret_cast<uint4*>(base + SWZ128((uint32_t)(row * 128 + c * 16))) = r;
    }
}

__device__ __forceinline__ void fill_Bd(char* base, int hh, int kc, int tid) {
    uint32_t bB = smem_u32(base + 16384);
    #pragma unroll
    for (int t = 0; t < 4; ++t) {
        int i = tid + t * 256;            // 0..1023 (128 rows x 8 chunks)
        int row = i >> 3, c = i & 7;
        int goff = (hh * 128 + row) * DD + kc * 32 + c * 4;
        CP_ASYNC16(bB + SWZ128((uint32_t)(row * 128 + c * 16)), (const void*)&g_Wd32[goff]);
    }
}

__device__ __forceinline__ void mma_ksd(int ks, uint32_t aA, uint32_t aB,
                                        int a_row, int a_cb, int b_row, int b_cb,
                                        float (&acc)[4][4][4]) {
    const int k0b = ks * 32;
    uint32_t a[4][4];
    #pragma unroll
    for (int m = 0; m < 4; ++m)
        ldm_x4(a[m], aA + SWZ128((uint32_t)((a_row + m * 16) * 128 + k0b + a_cb)));
    #pragma unroll
    for (int n = 0; n < 4; ++n) {
        uint32_t bf[2];
        ldm_x2(bf, aB + SWZ128((uint32_t)((b_row + n * 8) * 128 + k0b + b_cb)));
        #pragma unroll
        for (int m = 0; m < 4; ++m) mma_tf32(acc[m][n], a[m], bf);
    }
}

__global__ __launch_bounds__(256, 2)
void branchd_kernel(const float* __restrict__ Hp, const float* __restrict__ Hq,
                    const float* __restrict__ vd) {
    extern __shared__ char dsm[];
    const uint32_t sb = smem_u32(dsm);
    const int qh = blockIdx.x >> 1, hh = blockIdx.x & 1;
    const int p = blockIdx.y, b = blockIdx.z;
    const int tid = threadIdx.x, lane = tid & 31, warp = tid >> 5;
    const int wq = warp >> 2, wh = warp & 3;

    float* hp_s = reinterpret_cast<float*>(dsm + OFF_HP);
    float* vd_s = reinterpret_cast<float*>(dsm + OFF_VD);
    float* sdp  = reinterpret_cast<float*>(dsm + OFF_SDP);
    hp_s[tid] = Hp[(b * LL + p) * DD + tid];
    vd_s[tid] = vd[tid];
    if (tid < 128) sdp[tid] = 0.f;
    __syncthreads();

    const int a_row = wq * 64 + (lane & 15);
    const int a_cb  = (lane >> 4) * 16;
    const int b_row = wh * 32 + (lane & 7);
    const int b_cb  = ((lane >> 3) & 1) * 16;

    const float* hq_b = Hq + (b * LL) * DD;

    float acc[4][4][4];
    #pragma unroll
    for (int m = 0; m < 4; ++m)
        #pragma unroll
        for (int n = 0; n < 4; ++n)
            #pragma unroll
            for (int e = 0; e < 4; ++e) acc[m][n][e] = 0.f;

    // prologue: fill chunk 0
    {
        float4 pf[4];
        ldA_regs(pf, hq_b, qh, 0, tid);
        stA_regs(dsm, pf, hp_s, 0, tid);
        fill_Bd(dsm, hh, 0, tid);
        CP_COMMIT();
        CP_WAIT0();
        __syncthreads();
    }

    for (int kc = 0; kc < 8; ++kc) {
        const uint32_t aA = sb + (uint32_t)(kc & 1) * BUFSZ;
        const uint32_t aB = aA + 16384;
        char* nbase = dsm + ((kc + 1) & 1) * BUFSZ;

        float4 pf[4];
        if (kc < 7) {
            ldA_regs(pf, hq_b, qh, kc + 1, tid);   // LDGs in flight during MMAs
            fill_Bd(nbase, hh, kc + 1, tid);
            CP_COMMIT();
        }

        mma_ksd(0, aA, aB, a_row, a_cb, b_row, b_cb, acc);
        mma_ksd(1, aA, aB, a_row, a_cb, b_row, b_cb, acc);
        mma_ksd(2, aA, aB, a_row, a_cb, b_row, b_cb, acc);

        if (kc < 7) stA_regs(nbase, pf, hp_s, kc + 1, tid);

        mma_ksd(3, aA, aB, a_row, a_cb, b_row, b_cb, acc);

        if (kc < 7) CP_WAIT0();
        __syncthreads();
    }

    // epilogue: sdp[q_local] += sum over this CTA's 128 h of tanh(T)*vd
    #pragma unroll
    for (int m = 0; m < 4; ++m) {
        float s0 = 0.f, s1 = 0.f;
        #pragma unroll
        for (int n = 0; n < 4; ++n) {
            int h = hh * 128 + wh * 32 + n * 8 + (lane & 3) * 2;
            s0 = fmaf(tanh_fast(acc[m][n][0]), vd_s[h],     s0);
            s0 = fmaf(tanh_fast(acc[m][n][1]), vd_s[h + 1], s0);
            s1 = fmaf(tanh_fast(acc[m][n][2]), vd_s[h],     s1);
            s1 = fmaf(tanh_fast(acc[m][n][3]), vd_s[h + 1], s1);
        }
        s0 += __shfl_xor_sync(0xffffffffu, s0, 1);
        s0 += __shfl_xor_sync(0xffffffffu, s0, 2);
        s1 += __shfl_xor_sync(0xffffffffu, s1, 1);
        s1 += __shfl_xor_sync(0xffffffffu, s1, 2);
        if ((lane & 3) == 0) {
            int ql = wq * 64 + m * 16 + (lane >> 2);
            atomicAdd(&sdp[ql], s0);
            atomicAdd(&sdp[ql + 8], s1);
        }
    }
    __syncthreads();
    if (tid < 128) {
        float* dst = hh ? g_SD1 : g_SD0;
        dst[(b * LL + p) * LL + qh * 128 + tid] = sdp[tid];
    }
}

// ======================= kernel 3 (F1): scores c, b, m (r8 exact) =======================
__global__ __launch_bounds__(256, 2)
void score_kernel(const float* __restrict__ Hp,
                  const float* __restrict__ vc, const float* __restrict__ vm) {
    __shared__ float s1c[2][8][256];
    __shared__ float m1c[2][8][256];
    __shared__ float gc [2][8][256];

    const int q0 = blockIdx.x * 64, p0 = blockIdx.y * 16, b = blockIdx.z;
    const int tid = threadIdx.x, lane = tid & 31, w = tid >> 5;

    float s2v[2][8], m2v[2][8], hpv[2][8], vcv[8], vmv[8];
    #pragma unroll
    for (int i = 0; i < 8; ++i) {
        int h = lane + 32 * i;
        vcv[i] = vc[h];
        vmv[i] = vm[h];
        #pragma unroll
        for (int pi = 0; pi < 2; ++pi) {
            int p = p0 + w + 8 * pi;
            s2v[pi][i] = g_S2[(b * LL + p) * HH + h];
            m2v[pi][i] = g_M2[(b * LL + p) * HH + h];
            hpv[pi][i] = Hp  [(b * LL + p) * DD + h];
        }
    }

    auto issue_chunk = [&](int c, int cb) {
        #pragma unroll
        for (int t = 0; t < 6; ++t) {
            int i = tid + t * 256;
            int arr = i >> 9, rem = i & 511, row = rem >> 6, c16 = rem & 63;
            int gidx = (b * LL + q0 + c * 8 + row) * HH + c16 * 4;
            const float* src;
            float* dst;
            if (arr == 0)      { src = &g_S1[gidx]; dst = &s1c[cb][row][c16 * 4]; }
            else if (arr == 1) { src = &g_M1[gidx]; dst = &m1c[cb][row][c16 * 4]; }
            else               { src = &g_G [gidx]; dst = &gc [cb][row][c16 * 4]; }
            CP_ASYNC16(smem_u32(dst), (const void*)src);
        }
        CP_COMMIT();
    };

    issue_chunk(0, 0);
    for (int c = 0; c < 8; ++c) {
        int cb = c & 1;
        if (c < 7) { issue_chunk(c + 1, (c + 1) & 1); CP_WAIT1(); }
        else       { CP_WAIT0(); }
        __syncthreads();

        #pragma unroll
        for (int pi = 0; pi < 2; ++pi) {
            #pragma unroll 2
            for (int r = 0; r < 8; ++r) {
                float ac = 0.f, am = 0.f, ab = 0.f;
                #pragma unroll
                for (int i = 0; i < 8; ++i) {
                    int h = lane + 32 * i;
                    float s1 = s1c[cb][r][h];
                    float m1 = m1c[cb][r][h];
                    float g  = gc [cb][r][h];
                    ac = fmaf(tanh_fast(s1 + s2v[pi][i]), vcv[i], ac);
                    am = fmaf(tanh_fast(m1 - m2v[pi][i]), vmv[i], am);
                    ab = fmaf(hpv[pi][i], g, ab);
                }
                #pragma unroll
                for (int o = 16; o; o >>= 1) {
                    ac += __shfl_xor_sync(0xffffffffu, ac, o);
                    am += __shfl_xor_sync(0xffffffffu, am, o);
                    ab += __shfl_xor_sync(0xffffffffu, ab, o);
                }
                if (lane == 0) {
                    int p = p0 + w + 8 * pi;
                    int q = q0 + c * 8 + r;
                    int idx = (b * LL + p) * LL + q;
                    g_SC[idx] = ac;
                    g_SB[idx] = ab;
                    g_SM[idx] = am;
                }
            }
        }
        __syncthreads();
    }
}

// ======================= kernel 4 (F2): softmax + attend =======================
__global__ __launch_bounds__(256)
void attend_kernel(const float* __restrict__ Hq, float* __restrict__ out) {
    __shared__ float wsm[256][36];

    const int p0 = blockIdx.x * 8, b = blockIdx.y;
    const int tid = threadIdx.x, lane = tid & 31, w = tid >> 5;

    #pragma unroll
    for (int t = 0; t < 32; ++t) {
        int i = tid + t * 256;
        int p = i >> 10, br = (i >> 8) & 3, q = i & 255;
        int gi = (b * LL + p0 + p) * LL + q;
        float v;
        if      (br == 0) v = g_SC[gi];
        else if (br == 1) v = g_SB[gi];
        else if (br == 2) v = g_SD0[gi] + g_SD1[gi];
        else              v = g_SM[gi];
        wsm[q][p * 4 + br] = v;
    }
    __syncthreads();

    #pragma unroll
    for (int s = 0; s < 4; ++s) {
        int slot = w + 8 * s;
        float v[8];
        #pragma unroll
        for (int i = 0; i < 8; ++i) v[i] = wsm[lane + 32 * i][slot];
        float mx = v[0];
        #pragma unroll
        for (int i = 1; i < 8; ++i) mx = fmaxf(mx, v[i]);
        #pragma unroll
        for (int o = 16; o; o >>= 1) mx = fmaxf(mx, __shfl_xor_sync(0xffffffffu, mx, o));
        float sum = 0.f;
        #pragma unroll
        for (int i = 0; i < 8; ++i) { v[i] = __expf(v[i] - mx); sum += v[i]; }
        #pragma unroll
        for (int o = 16; o; o >>= 1) sum += __shfl_xor_sync(0xffffffffu, sum, o);
        float inv = 1.0f / sum;
        #pragma unroll
        for (int i = 0; i < 8; ++i) wsm[lane + 32 * i][slot] = v[i] * inv;
    }
    __syncthreads();

    float acc[32];
    #pragma unroll
    for (int s = 0; s < 32; ++s) acc[s] = 0.f;
    const float* hqb = &Hq[(b * LL) * DD + tid];
    #pragma unroll 4
    for (int q = 0; q < LL; ++q) {
        float hq = hqb[q * DD];
        #pragma unroll
        for (int j = 0; j < 8; ++j) {
            float4 wv = *reinterpret_cast<const float4*>(&wsm[q][j * 4]);
            acc[j * 4 + 0] = fmaf(wv.x, hq, acc[j * 4 + 0]);
            acc[j * 4 + 1] = fmaf(wv.y, hq, acc[j * 4 + 1]);
            acc[j * 4 + 2] = fmaf(wv.z, hq, acc[j * 4 + 2]);
            acc[j * 4 + 3] = fmaf(wv.w, hq, acc[j * 4 + 3]);
        }
    }
    const int BR = BB * LL * DD;
    #pragma unroll
    for (int p = 0; p < 8; ++p)
        #pragma unroll
        for (int br = 0; br < 4; ++br)
            out[br * BR + (b * LL + p0 + p) * DD + tid] = acc[p * 4 + br];
}

// ======================= launch =======================
extern "C" void kernel_launch(void* const* d_in, const int* in_sizes, int n_in,
                              void* d_out, int out_size) {
    (void)in_sizes; (void)n_in; (void)out_size;
    const float* Hp  = (const float*)d_in[0];
    const float* Hq  = (const float*)d_in[1];
    const float* Wc1 = (const float*)d_in[2];
    const float* Wc2 = (const float*)d_in[3];
    const float* vc  = (const float*)d_in[4];
    const float* Wb  = (const float*)d_in[5];
    const float* Wd  = (const float*)d_in[6];
    const float* vd  = (const float*)d_in[7];
    const float* Wm  = (const float*)d_in[8];
    const float* vm  = (const float*)d_in[9];
    float* out = (float*)d_out;

    cudaFuncSetAttribute(branchd_kernel,
                         cudaFuncAttributeMaxDynamicSharedMemorySize, SMEM_D);
    cudaFuncSetAttribute(projmma_kernel,
                         cudaFuncAttributeMaxDynamicSharedMemorySize, SMEM_P);

    dim3 gw(256, 4);
    prep_w_kernel<<<gw, 256>>>(Wc1, Wc2, Wm, Wd);

    projmma_kernel<<<128, 256, SMEM_P>>>(Hp, Hq);

    dim3 gb(16, 4);
    projb_kernel<<<gb, 256>>>(Hq, Wb);

    dim3 gd(4, LL, BB);
    branchd_kernel<<<gd, 256, SMEM_D>>>(Hp, Hq, vd);

    dim3 gs(4, 16, 4);
    score_kernel<<<gs, 256>>>(Hp, vc, vm);

    dim3 ga(32, 4);
    attend_kernel<<<ga, 256>>>(Hq, out);
}

// round 16
// speedup vs baseline: 1.0935x; 1.0935x over previous
#include <cuda_runtime.h>
#include <cuda_bf16.h>
#include <cstdint>

// Problem: B=4, Lp=Lq=256, D=256, H=256.
// Inputs: Hp, Hq, Wc1, Wc2, vc, Wb, Wd, vd, Wm, vm (all fp32)
// Output: concat(qc, qb, qd, qm), each (B, Lp, D) fp32.

#define BB 4
#define LL 256
#define DD 256
#define HH 256

// -------- scratch (static device globals; no allocation allowed) --------
__device__ float g_S1[BB * LL * HH];
__device__ float g_S2[BB * LL * HH];
__device__ float g_G [BB * LL * HH];
__device__ float g_M1[BB * LL * HH];
__device__ float g_M2[BB * LL * HH];
__device__ float g_SD[BB * LL * LL];
__device__ float g_SC[BB * LL * LL];
__device__ float g_SB[BB * LL * LL];
__device__ float g_SM[BB * LL * LL];
__device__ uint32_t g_Wd32[HH * DD];      // Wd^T in tf32 bits [h][k]
__device__ uint32_t g_WT32[3][DD * HH];   // {Wc1,Wc2,Wm}^T in tf32 bits [n][k]

// ======================= helpers =======================
__device__ __forceinline__ uint32_t smem_u32(const void* p) {
    uint32_t a;
    asm("{ .reg .u64 t; cvta.to.shared.u64 t, %1; cvt.u32.u64 %0, t; }"
        : "=r"(a) : "l"(p));
    return a;
}

__device__ __forceinline__ float tanh_fast(float x) {
    float y;
    asm("tanh.approx.f32 %0, %1;" : "=f"(y) : "f"(x));
    return y;
}

__device__ __forceinline__ uint32_t tf32_of(float f) {
    uint32_t u;
    asm("cvt.rna.tf32.f32 %0, %1;" : "=r"(u) : "f"(f));
    return u;
}

#define SWZ128(off) ((off) ^ (((off) >> 3) & 0x70))

#define CP_ASYNC16(dst_u32, src_ptr) \
    asm volatile("cp.async.cg.shared.global [%0], [%1], 16;" \
                 :: "r"(dst_u32), "l"(src_ptr) : "memory")
#define CP_COMMIT() asm volatile("cp.async.commit_group;" ::: "memory")
#define CP_WAIT0()  asm volatile("cp.async.wait_group 0;" ::: "memory")
#define CP_WAIT1()  asm volatile("cp.async.wait_group 1;" ::: "memory")

__device__ __forceinline__ void ldm_x4(uint32_t* r, uint32_t addr) {
    asm volatile("ldmatrix.sync.aligned.m8n8.x4.shared.b16 {%0,%1,%2,%3}, [%4];"
                 : "=r"(r[0]), "=r"(r[1]), "=r"(r[2]), "=r"(r[3]) : "r"(addr));
}

__device__ __forceinline__ void ldm_x2(uint32_t* r, uint32_t addr) {
    asm volatile("ldmatrix.sync.aligned.m8n8.x2.shared.b16 {%0,%1}, [%2];"
                 : "=r"(r[0]), "=r"(r[1]) : "r"(addr));
}

__device__ __forceinline__ void mma_tf32(float* d, const uint32_t* a, const uint32_t* b) {
    asm volatile(
        "mma.sync.aligned.m16n8k8.row.col.f32.tf32.tf32.f32 "
        "{%0,%1,%2,%3}, {%4,%5,%6,%7}, {%8,%9}, {%0,%1,%2,%3};"
        : "+f"(d[0]), "+f"(d[1]), "+f"(d[2]), "+f"(d[3])
        : "r"(a[0]), "r"(a[1]), "r"(a[2]), "r"(a[3]), "r"(b[0]), "r"(b[1]));
}

// ======================= kernel 0: weight transposes -> tf32 =======================
__global__ void prep_w_kernel(const float* __restrict__ Wc1, const float* __restrict__ Wc2,
                              const float* __restrict__ Wm,  const float* __restrict__ Wd) {
    int k = blockIdx.x, n = threadIdx.x, w = blockIdx.y;
    const float* src = (w == 0) ? Wc1 : (w == 1) ? Wc2 : (w == 2) ? Wm : Wd;
    uint32_t v = tf32_of(src[k * 256 + n]);
    if (w < 3) g_WT32[w][n * 256 + k] = v;
    else       g_Wd32[n * 256 + k] = v;
}

// ======================= kernel 1a: 4 tanh-gated projections via tf32 mma =======================
static constexpr int PBUF = 24576;   // A 8KB + B 16KB
static constexpr int SMEM_P = 2 * PBUF;  // 48KB

__global__ __launch_bounds__(256)
void projmma_kernel(const float* __restrict__ Hp, const float* __restrict__ Hq) {
    extern __shared__ char psm[];
    const uint32_t sb = smem_u32(psm);
    const int bx = blockIdx.x;
    const int gemm = bx >> 5;
    const int rr = bx & 31;
    const int mb = (rr >> 1) * 64, nb = (rr & 1) * 128;
    const float* A = (gemm == 1 || gemm == 3) ? Hp : Hq;
    const uint32_t* WT = g_WT32[gemm < 2 ? gemm : 2];
    float* C = (gemm == 0) ? g_S1 : (gemm == 1) ? g_S2 : (gemm == 2) ? g_M1 : g_M2;

    const int tid = threadIdx.x, lane = tid & 31, warp = tid >> 5;
    const int wm = warp >> 1, wn = warp & 1;

    const int a_row  = wm * 16 + (lane & 15);
    const int a_cb   = (lane >> 4) * 16;
    const int b_row2 = wn * 64 + ((lane >> 4) & 1) * 8 + (lane & 7);
    const int b_cb2  = ((lane >> 3) & 1) * 16;

    float acc[8][4];
    #pragma unroll
    for (int n = 0; n < 8; ++n)
        #pragma unroll
        for (int e = 0; e < 4; ++e) acc[n][e] = 0.f;

    auto fillA = [&](char* base, int kc) {
        #pragma unroll
        for (int t = 0; t < 2; ++t) {
            int i = tid + t * 256;
            int row = i >> 3, c = i & 7;
            float4 v = *reinterpret_cast<const float4*>(
                &A[(mb + row) * 256 + kc * 32 + c * 4]);
            uint4 u;
            u.x = tf32_of(v.x); u.y = tf32_of(v.y);
            u.z = tf32_of(v.z); u.w = tf32_of(v.w);
            *reinterpret_cast<uint4*>(base + SWZ128((uint32_t)(row * 128 + c * 16))) = u;
        }
    };
    auto fillB = [&](char* base, int kc) {
        uint32_t bB = smem_u32(base + 8192);
        #pragma unroll
        for (int t = 0; t < 4; ++t) {
            int i = tid + t * 256;
            int row = i >> 3, c = i & 7;
            CP_ASYNC16(bB + SWZ128((uint32_t)(row * 128 + c * 16)),
                       (const void*)&WT[(nb + row) * 256 + kc * 32 + c * 4]);
        }
        CP_COMMIT();
    };

    fillA(psm, 0);
    fillB(psm, 0);
    CP_WAIT0();
    __syncthreads();

    for (int kc = 0; kc < 8; ++kc) {
        char* nxt = psm + ((kc + 1) & 1) * PBUF;
        const uint32_t aA = sb + (uint32_t)(kc & 1) * PBUF;
        const uint32_t aB = aA + 8192;

        if (kc < 7) fillB(nxt, kc + 1);

        #pragma unroll
        for (int ks = 0; ks < 4; ++ks) {
            const int k0b = ks * 32;
            uint32_t a[4];
            ldm_x4(a, aA + SWZ128((uint32_t)(a_row * 128 + k0b + a_cb)));
            #pragma unroll
            for (int n2 = 0; n2 < 4; ++n2) {
                uint32_t bf[4];
                ldm_x4(bf, aB + SWZ128((uint32_t)((b_row2 + n2 * 16) * 128 + k0b + b_cb2)));
                mma_tf32(acc[2 * n2],     a, bf);
                mma_tf32(acc[2 * n2 + 1], a, bf + 2);
            }
        }

        if (kc < 7) { fillA(nxt, kc + 1); CP_WAIT0(); }
        __syncthreads();
    }

    const int r0 = mb + wm * 16 + (lane >> 2);
    #pragma unroll
    for (int n2 = 0; n2 < 4; ++n2)
        #pragma unroll
        for (int half = 0; half < 2; ++half) {
            int cb = nb + wn * 64 + n2 * 16 + half * 8 + (lane & 3) * 2;
            const float* a4 = acc[2 * n2 + half];
            C[r0 * 256 + cb]           = a4[0];
            C[r0 * 256 + cb + 1]       = a4[1];
            C[(r0 + 8) * 256 + cb]     = a4[2];
            C[(r0 + 8) * 256 + cb + 1] = a4[3];
        }
}

// ======================= kernel 1b: G = Hq @ Wb in fp32 =======================
__global__ void projb_kernel(const float* __restrict__ Hq, const float* __restrict__ Wb) {
    const int mb = blockIdx.x * 64, nb = blockIdx.y * 64;
    const int tid = threadIdx.x, ty = tid >> 4, tx = tid & 15;

    __shared__ float As[16][68];
    __shared__ float Bs[16][68];

    float acc[4][4] = {};
    for (int kt = 0; kt < 16; ++kt) {
        {
            int m = tid >> 2, k4 = (tid & 3) * 4;
            float4 v = *reinterpret_cast<const float4*>(&Hq[(mb + m) * 256 + kt * 16 + k4]);
            As[k4 + 0][m] = v.x; As[k4 + 1][m] = v.y;
            As[k4 + 2][m] = v.z; As[k4 + 3][m] = v.w;
        }
        {
            int k = tid >> 4, n4 = (tid & 15) * 4;
            float4 v = *reinterpret_cast<const float4*>(&Wb[(kt * 16 + k) * 256 + nb + n4]);
            *reinterpret_cast<float4*>(&Bs[k][n4]) = v;
        }
        __syncthreads();
        #pragma unroll
        for (int k = 0; k < 16; ++k) {
            float a[4], bv[4];
            #pragma unroll
            for (int i = 0; i < 4; ++i) a[i] = As[k][ty + 16 * i];
            #pragma unroll
            for (int j = 0; j < 4; ++j) bv[j] = Bs[k][tx + 16 * j];
            #pragma unroll
            for (int i = 0; i < 4; ++i)
                #pragma unroll
                for (int j = 0; j < 4; ++j) acc[i][j] = fmaf(a[i], bv[j], acc[i][j]);
        }
        __syncthreads();
    }
    #pragma unroll
    for (int i = 0; i < 4; ++i)
        #pragma unroll
        for (int j = 0; j < 4; ++j)
            g_G[(mb + ty + 16 * i) * 256 + nb + tx + 16 * j] = acc[i][j];
}

// ======================= kernel 2: branch d — tf32 mma, LDG-prefetch (r11 exact) =======================
static constexpr int BUFSZ   = 49152;
static constexpr int OFF_HP  = 2 * BUFSZ;
static constexpr int OFF_VD  = OFF_HP + 1024;
static constexpr int OFF_SDP = OFF_VD + 1024;
static constexpr int SMEM_D  = OFF_SDP + 1024;    // 101376

__device__ __forceinline__ void ldA_regs(float4 (&pf)[4], const float* __restrict__ hq_b,
                                         int qh, int kc, int tid) {
    #pragma unroll
    for (int t = 0; t < 4; ++t) {
        int i = tid + t * 256;
        int row = i >> 3, c = i & 7;
        pf[t] = *reinterpret_cast<const float4*>(
            &hq_b[(qh * 128 + row) * DD + kc * 32 + c * 4]);
    }
}

__device__ __forceinline__ void stA_regs(char* base, const float4 (&pf)[4],
                                         const float* hp_s, int kc, int tid) {
    #pragma unroll
    for (int t = 0; t < 4; ++t) {
        int i = tid + t * 256;
        int row = i >> 3, c = i & 7;
        int kg = kc * 32 + c * 4;
        uint4 r;
        r.x = tf32_of(pf[t].x * hp_s[kg + 0]);
        r.y = tf32_of(pf[t].y * hp_s[kg + 1]);
        r.z = tf32_of(pf[t].z * hp_s[kg + 2]);
        r.w = tf32_of(pf[t].w * hp_s[kg + 3]);
        *reinterpret_cast<uint4*>(base + SWZ128((uint32_t)(row * 128 + c * 16))) = r;
    }
}

__device__ __forceinline__ void fill_Bd(char* base, int kc, int tid) {
    uint32_t bB = smem_u32(base + 16384);
    #pragma unroll
    for (int t = 0; t < 8; ++t) {
        int i = tid + t * 256;
        int row = i >> 3, c = i & 7;
        int goff = row * DD + kc * 32 + c * 4;
        CP_ASYNC16(bB + SWZ128((uint32_t)(row * 128 + c * 16)), (const void*)&g_Wd32[goff]);
    }
}

__device__ __forceinline__ void mma_ksd(int ks, uint32_t aA, uint32_t aB,
                                        int a_row, int a_cb, int b_row, int b_cb, int wh,
                                        float (&acc)[4][8][4]) {
    const int k0b = ks * 32;
    uint32_t a[4][4];
    #pragma unroll
    for (int m = 0; m < 4; ++m) {
        uint32_t offA = SWZ128((uint32_t)((a_row + m * 16) * 128 + k0b + a_cb));
        ldm_x4(a[m], aA + offA);
    }
    #pragma unroll
    for (int n = 0; n < 8; ++n) {
        uint32_t offB = SWZ128((uint32_t)((b_row + n * 8) * 128 + k0b + b_cb));
        uint32_t bf[2];
        ldm_x2(bf, aB + offB);
        #pragma unroll
        for (int m = 0; m < 4; ++m) mma_tf32(acc[m][n], a[m], bf);
    }
}

__global__ __launch_bounds__(256, 1)
void branchd_kernel(const float* __restrict__ Hp, const float* __restrict__ Hq,
                    const float* __restrict__ vd) {
    extern __shared__ char dsm[];
    const uint32_t sb = smem_u32(dsm);
    const int p = blockIdx.x, b = blockIdx.y;
    const int tid = threadIdx.x, lane = tid & 31, warp = tid >> 5;
    const int wq = warp >> 2, wh = warp & 3;

    float* hp_s = reinterpret_cast<float*>(dsm + OFF_HP);
    float* vd_s = reinterpret_cast<float*>(dsm + OFF_VD);
    float* sdp  = reinterpret_cast<float*>(dsm + OFF_SDP);
    hp_s[tid] = Hp[(b * LL + p) * DD + tid];
    vd_s[tid] = vd[tid];
    sdp[tid] = 0.f;
    __syncthreads();

    const int a_row = wq * 64 + (lane & 15);
    const int a_cb  = (lane >> 4) * 16;
    const int b_row = wh * 64 + (lane & 7);
    const int b_cb  = ((lane >> 3) & 1) * 16;

    const float* hq_b = Hq + (b * LL) * DD;

    {
        float4 pf[4];
        ldA_regs(pf, hq_b, 0, 0, tid);
        stA_regs(dsm, pf, hp_s, 0, tid);
        fill_Bd(dsm, 0, tid);
        CP_COMMIT();
        CP_WAIT0();
        __syncthreads();
    }

    for (int qh = 0; qh < 2; ++qh) {
        float acc[4][8][4];
        #pragma unroll
        for (int m = 0; m < 4; ++m)
            #pragma unroll
            for (int n = 0; n < 8; ++n)
                #pragma unroll
                for (int e = 0; e < 4; ++e) acc[m][n][e] = 0.f;

        for (int kc = 0; kc < 8; ++kc) {
            const int t = qh * 8 + kc;
            const uint32_t aA = sb + (uint32_t)(t & 1) * BUFSZ;
            const uint32_t aB = aA + 16384;
            char* nbase = dsm + ((t + 1) & 1) * BUFSZ;

            float4 pf[4];
            if (t < 15) {
                ldA_regs(pf, hq_b, (t + 1) >> 3, (t + 1) & 7, tid);
                fill_Bd(nbase, (t + 1) & 7, tid);
                CP_COMMIT();
            }

            mma_ksd(0, aA, aB, a_row, a_cb, b_row, b_cb, wh, acc);
            mma_ksd(1, aA, aB, a_row, a_cb, b_row, b_cb, wh, acc);
            mma_ksd(2, aA, aB, a_row, a_cb, b_row, b_cb, wh, acc);

            if (t < 15) stA_regs(nbase, pf, hp_s, (t + 1) & 7, tid);

            mma_ksd(3, aA, aB, a_row, a_cb, b_row, b_cb, wh, acc);

            if (t < 15) CP_WAIT0();
            __syncthreads();
        }
        #pragma unroll
        for (int m = 0; m < 4; ++m) {
            float s0 = 0.f, s1 = 0.f;
            #pragma unroll
            for (int n = 0; n < 8; ++n) {
                int h = wh * 64 + n * 8 + (lane & 3) * 2;
                s0 = fmaf(tanh_fast(acc[m][n][0]), vd_s[h],     s0);
                s0 = fmaf(tanh_fast(acc[m][n][1]), vd_s[h + 1], s0);
                s1 = fmaf(tanh_fast(acc[m][n][2]), vd_s[h],     s1);
                s1 = fmaf(tanh_fast(acc[m][n][3]), vd_s[h + 1], s1);
            }
            s0 += __shfl_xor_sync(0xffffffffu, s0, 1);
            s0 += __shfl_xor_sync(0xffffffffu, s0, 2);
            s1 += __shfl_xor_sync(0xffffffffu, s1, 1);
            s1 += __shfl_xor_sync(0xffffffffu, s1, 2);
            if ((lane & 3) == 0) {
                int q = qh * 128 + wq * 64 + m * 16 + (lane >> 2);
                atomicAdd(&sdp[q], s0);
                atomicAdd(&sdp[q + 8], s1);
            }
        }
    }
    __syncthreads();
    g_SD[(b * LL + p) * LL + tid] = sdp[tid];
}

// ======================= kernel 3 (F1): scores c, b, m — vectorized h-major =======================
// Warp w handles p_a = p0+w and p_b = p0+w+8. Lane covers h = {4*lane..4*lane+3, 128+4*lane..+3}.
__global__ __launch_bounds__(256, 2)
void score_kernel(const float* __restrict__ Hp,
                  const float* __restrict__ vc, const float* __restrict__ vm) {
    __shared__ __align__(16) float s1c[2][8][256];
    __shared__ __align__(16) float m1c[2][8][256];
    __shared__ __align__(16) float gc [2][8][256];

    const int q0 = blockIdx.x * 64, p0 = blockIdx.y * 16, b = blockIdx.z;
    const int tid = threadIdx.x, lane = tid & 31, w = tid >> 5;
    const int hA = 4 * lane, hB = 128 + 4 * lane;

    // per-lane fp32x4 constants
    const float4 vc4a = *reinterpret_cast<const float4*>(&vc[hA]);
    const float4 vc4b = *reinterpret_cast<const float4*>(&vc[hB]);
    const float4 vm4a = *reinterpret_cast<const float4*>(&vm[hA]);
    const float4 vm4b = *reinterpret_cast<const float4*>(&vm[hB]);

    float4 s2a[2], s2b[2], m2a[2], m2b[2], hpa[2], hpb[2];
    #pragma unroll
    for (int pi = 0; pi < 2; ++pi) {
        int p = p0 + w + 8 * pi;
        s2a[pi] = *reinterpret_cast<const float4*>(&g_S2[(b * LL + p) * HH + hA]);
        s2b[pi] = *reinterpret_cast<const float4*>(&g_S2[(b * LL + p) * HH + hB]);
        m2a[pi] = *reinterpret_cast<const float4*>(&g_M2[(b * LL + p) * HH + hA]);
        m2b[pi] = *reinterpret_cast<const float4*>(&g_M2[(b * LL + p) * HH + hB]);
        hpa[pi] = *reinterpret_cast<const float4*>(&Hp[(b * LL + p) * DD + hA]);
        hpb[pi] = *reinterpret_cast<const float4*>(&Hp[(b * LL + p) * DD + hB]);
    }

    auto issue_chunk = [&](int c, int cb) {
        #pragma unroll
        for (int t = 0; t < 6; ++t) {
            int i = tid + t * 256;
            int arr = i >> 9, rem = i & 511, row = rem >> 6, c16 = rem & 63;
            int gidx = (b * LL + q0 + c * 8 + row) * HH + c16 * 4;
            const float* src;
            float* dst;
            if (arr == 0)      { src = &g_S1[gidx]; dst = &s1c[cb][row][c16 * 4]; }
            else if (arr == 1) { src = &g_M1[gidx]; dst = &m1c[cb][row][c16 * 4]; }
            else               { src = &g_G [gidx]; dst = &gc [cb][row][c16 * 4]; }
            CP_ASYNC16(smem_u32(dst), (const void*)src);
        }
        CP_COMMIT();
    };

    issue_chunk(0, 0);
    for (int c = 0; c < 8; ++c) {
        int cb = c & 1;
        if (c < 7) { issue_chunk(c + 1, (c + 1) & 1); CP_WAIT1(); }
        else       { CP_WAIT0(); }
        __syncthreads();

        #pragma unroll 2
        for (int r = 0; r < 8; ++r) {
            // pi-invariant row fragments: 6 x LDS.128
            const float4 s1a = *reinterpret_cast<const float4*>(&s1c[cb][r][hA]);
            const float4 s1b = *reinterpret_cast<const float4*>(&s1c[cb][r][hB]);
            const float4 m1a = *reinterpret_cast<const float4*>(&m1c[cb][r][hA]);
            const float4 m1b = *reinterpret_cast<const float4*>(&m1c[cb][r][hB]);
            const float4 ga  = *reinterpret_cast<const float4*>(&gc [cb][r][hA]);
            const float4 gb  = *reinterpret_cast<const float4*>(&gc [cb][r][hB]);

            float red[6];
            #pragma unroll
            for (int pi = 0; pi < 2; ++pi) {
                float ac, am, ab;
                ac  = tanh_fast(s1a.x + s2a[pi].x) * vc4a.x;
                ac  = fmaf(tanh_fast(s1a.y + s2a[pi].y), vc4a.y, ac);
                ac  = fmaf(tanh_fast(s1a.z + s2a[pi].z), vc4a.z, ac);
                ac  = fmaf(tanh_fast(s1a.w + s2a[pi].w), vc4a.w, ac);
                ac  = fmaf(tanh_fast(s1b.x + s2b[pi].x), vc4b.x, ac);
                ac  = fmaf(tanh_fast(s1b.y + s2b[pi].y), vc4b.y, ac);
                ac  = fmaf(tanh_fast(s1b.z + s2b[pi].z), vc4b.z, ac);
                ac  = fmaf(tanh_fast(s1b.w + s2b[pi].w), vc4b.w, ac);

                am  = tanh_fast(m1a.x - m2a[pi].x) * vm4a.x;
                am  = fmaf(tanh_fast(m1a.y - m2a[pi].y), vm4a.y, am);
                am  = fmaf(tanh_fast(m1a.z - m2a[pi].z), vm4a.z, am);
                am  = fmaf(tanh_fast(m1a.w - m2a[pi].w), vm4a.w, am);
                am  = fmaf(tanh_fast(m1b.x - m2b[pi].x), vm4b.x, am);
                am  = fmaf(tanh_fast(m1b.y - m2b[pi].y), vm4b.y, am);
                am  = fmaf(tanh_fast(m1b.z - m2b[pi].z), vm4b.z, am);
                am  = fmaf(tanh_fast(m1b.w - m2b[pi].w), vm4b.w, am);

                ab  = hpa[pi].x * ga.x;
                ab  = fmaf(hpa[pi].y, ga.y, ab);
                ab  = fmaf(hpa[pi].z, ga.z, ab);
                ab  = fmaf(hpa[pi].w, ga.w, ab);
                ab  = fmaf(hpb[pi].x, gb.x, ab);
                ab  = fmaf(hpb[pi].y, gb.y, ab);
                ab  = fmaf(hpb[pi].z, gb.z, ab);
                ab  = fmaf(hpb[pi].w, gb.w, ab);

                red[3 * pi + 0] = ac;
                red[3 * pi + 1] = ab;
                red[3 * pi + 2] = am;
            }
            // 6 interleaved butterfly chains
            #pragma unroll
            for (int o = 16; o; o >>= 1)
                #pragma unroll
                for (int j = 0; j < 6; ++j)
                    red[j] += __shfl_xor_sync(0xffffffffu, red[j], o);
            if (lane == 0) {
                int q = q0 + c * 8 + r;
                #pragma unroll
                for (int pi = 0; pi < 2; ++pi) {
                    int p = p0 + w + 8 * pi;
                    int idx = (b * LL + p) * LL + q;
                    g_SC[idx] = red[3 * pi + 0];
                    g_SB[idx] = red[3 * pi + 1];
                    g_SM[idx] = red[3 * pi + 2];
                }
            }
        }
        __syncthreads();
    }
}

// ======================= kernel 4 (F2): softmax + attend (r8 exact) =======================
__global__ __launch_bounds__(256)
void attend_kernel(const float* __restrict__ Hq, float* __restrict__ out) {
    __shared__ float wsm[256][36];

    const int p0 = blockIdx.x * 8, b = blockIdx.y;
    const int tid = threadIdx.x, lane = tid & 31, w = tid >> 5;

    const float* srcs[4] = {g_SC, g_SB, g_SD, g_SM};
    #pragma unroll
    for (int t = 0; t < 32; ++t) {
        int i = tid + t * 256;
        int p = i >> 10, br = (i >> 8) & 3, q = i & 255;
        wsm[q][p * 4 + br] = srcs[br][(b * LL + p0 + p) * LL + q];
    }
    __syncthreads();

    #pragma unroll
    for (int s = 0; s < 4; ++s) {
        int slot = w + 8 * s;
        float v[8];
        #pragma unroll
        for (int i = 0; i < 8; ++i) v[i] = wsm[lane + 32 * i][slot];
        float mx = v[0];
        #pragma unroll
        for (int i = 1; i < 8; ++i) mx = fmaxf(mx, v[i]);
        #pragma unroll
        for (int o = 16; o; o >>= 1) mx = fmaxf(mx, __shfl_xor_sync(0xffffffffu, mx, o));
        float sum = 0.f;
        #pragma unroll
        for (int i = 0; i < 8; ++i) { v[i] = __expf(v[i] - mx); sum += v[i]; }
        #pragma unroll
        for (int o = 16; o; o >>= 1) sum += __shfl_xor_sync(0xffffffffu, sum, o);
        float inv = 1.0f / sum;
        #pragma unroll
        for (int i = 0; i < 8; ++i) wsm[lane + 32 * i][slot] = v[i] * inv;
    }
    __syncthreads();

    float acc[32];
    #pragma unroll
    for (int s = 0; s < 32; ++s) acc[s] = 0.f;
    const float* hqb = &Hq[(b * LL) * DD + tid];
    #pragma unroll 4
    for (int q = 0; q < LL; ++q) {
        float hq = hqb[q * DD];
        #pragma unroll
        for (int j = 0; j < 8; ++j) {
            float4 wv = *reinterpret_cast<const float4*>(&wsm[q][j * 4]);
            acc[j * 4 + 0] = fmaf(wv.x, hq, acc[j * 4 + 0]);
            acc[j * 4 + 1] = fmaf(wv.y, hq, acc[j * 4 + 1]);
            acc[j * 4 + 2] = fmaf(wv.z, hq, acc[j * 4 + 2]);
            acc[j * 4 + 3] = fmaf(wv.w, hq, acc[j * 4 + 3]);
        }
    }
    const int BR = BB * LL * DD;
    #pragma unroll
    for (int p = 0; p < 8; ++p)
        #pragma unroll
        for (int br = 0; br < 4; ++br)
            out[br * BR + (b * LL + p0 + p) * DD + tid] = acc[p * 4 + br];
}

// ======================= launch =======================
extern "C" void kernel_launch(void* const* d_in, const int* in_sizes, int n_in,
                              void* d_out, int out_size) {
    (void)in_sizes; (void)n_in; (void)out_size;
    const float* Hp  = (const float*)d_in[0];
    const float* Hq  = (const float*)d_in[1];
    const float* Wc1 = (const float*)d_in[2];
    const float* Wc2 = (const float*)d_in[3];
    const float* vc  = (const float*)d_in[4];
    const float* Wb  = (const float*)d_in[5];
    const float* Wd  = (const float*)d_in[6];
    const float* vd  = (const float*)d_in[7];
    const float* Wm  = (const float*)d_in[8];
    const float* vm  = (const float*)d_in[9];
    float* out = (float*)d_out;

    cudaFuncSetAttribute(branchd_kernel,
                         cudaFuncAttributeMaxDynamicSharedMemorySize, SMEM_D);
    cudaFuncSetAttribute(projmma_kernel,
                         cudaFuncAttributeMaxDynamicSharedMemorySize, SMEM_P);

    dim3 gw(256, 4);
    prep_w_kernel<<<gw, 256>>>(Wc1, Wc2, Wm, Wd);

    projmma_kernel<<<128, 256, SMEM_P>>>(Hp, Hq);

    dim3 gb(16, 4);
    projb_kernel<<<gb, 256>>>(Hq, Wb);

    dim3 gd(LL, BB);
    branchd_kernel<<<gd, 256, SMEM_D>>>(Hp, Hq, vd);

    dim3 gs(4, 16, 4);
    score_kernel<<<gs, 256>>>(Hp, vc, vm);

    dim3 ga(32, 4);
    attend_kernel<<<ga, 256>>>(Hq, out);
}

// round 17
// speedup vs baseline: 1.1017x; 1.0076x over previous
#include <cuda_runtime.h>
#include <cuda_bf16.h>
#include <cstdint>

// Problem: B=4, Lp=Lq=256, D=256, H=256.
// Inputs: Hp, Hq, Wc1, Wc2, vc, Wb, Wd, vd, Wm, vm (all fp32)
// Output: concat(qc, qb, qd, qm), each (B, Lp, D) fp32.

#define BB 4
#define LL 256
#define DD 256
#define HH 256

// -------- scratch (static device globals; no allocation allowed) --------
__device__ float g_S1[BB * LL * HH];
__device__ float g_S2[BB * LL * HH];
__device__ float g_G [BB * LL * HH];
__device__ float g_M1[BB * LL * HH];
__device__ float g_M2[BB * LL * HH];
__device__ float g_SD[BB * LL * LL];
__device__ float g_SC[BB * LL * LL];
__device__ float g_SB[BB * LL * LL];
__device__ float g_SM[BB * LL * LL];
__device__ uint32_t g_Wd32[HH * DD];      // Wd^T in tf32 bits [h][k]
__device__ uint32_t g_WT32[3][DD * HH];   // {Wc1,Wc2,Wm}^T in tf32 bits [n][k]

// ======================= helpers =======================
__device__ __forceinline__ uint32_t smem_u32(const void* p) {
    uint32_t a;
    asm("{ .reg .u64 t; cvta.to.shared.u64 t, %1; cvt.u32.u64 %0, t; }"
        : "=r"(a) : "l"(p));
    return a;
}

__device__ __forceinline__ float tanh_fast(float x) {
    float y;
    asm("tanh.approx.f32 %0, %1;" : "=f"(y) : "f"(x));
    return y;
}

__device__ __forceinline__ uint32_t tf32_of(float f) {
    uint32_t u;
    asm("cvt.rna.tf32.f32 %0, %1;" : "=r"(u) : "f"(f));
    return u;
}

#define SWZ128(off) ((off) ^ (((off) >> 3) & 0x70))

#define CP_ASYNC16(dst_u32, src_ptr) \
    asm volatile("cp.async.cg.shared.global [%0], [%1], 16;" \
                 :: "r"(dst_u32), "l"(src_ptr) : "memory")
#define CP_COMMIT() asm volatile("cp.async.commit_group;" ::: "memory")
#define CP_WAIT0()  asm volatile("cp.async.wait_group 0;" ::: "memory")
#define CP_WAIT1()  asm volatile("cp.async.wait_group 1;" ::: "memory")

__device__ __forceinline__ void ldm_x4(uint32_t* r, uint32_t addr) {
    asm volatile("ldmatrix.sync.aligned.m8n8.x4.shared.b16 {%0,%1,%2,%3}, [%4];"
                 : "=r"(r[0]), "=r"(r[1]), "=r"(r[2]), "=r"(r[3]) : "r"(addr));
}

__device__ __forceinline__ void ldm_x2(uint32_t* r, uint32_t addr) {
    asm volatile("ldmatrix.sync.aligned.m8n8.x2.shared.b16 {%0,%1}, [%2];"
                 : "=r"(r[0]), "=r"(r[1]) : "r"(addr));
}

__device__ __forceinline__ void mma_tf32(float* d, const uint32_t* a, const uint32_t* b) {
    asm volatile(
        "mma.sync.aligned.m16n8k8.row.col.f32.tf32.tf32.f32 "
        "{%0,%1,%2,%3}, {%4,%5,%6,%7}, {%8,%9}, {%0,%1,%2,%3};"
        : "+f"(d[0]), "+f"(d[1]), "+f"(d[2]), "+f"(d[3])
        : "r"(a[0]), "r"(a[1]), "r"(a[2]), "r"(a[3]), "r"(b[0]), "r"(b[1]));
}

// ======================= kernel 0: weight transposes -> tf32 =======================
__global__ void prep_w_kernel(const float* __restrict__ Wc1, const float* __restrict__ Wc2,
                              const float* __restrict__ Wm,  const float* __restrict__ Wd) {
    int k = blockIdx.x, n = threadIdx.x, w = blockIdx.y;
    const float* src = (w == 0) ? Wc1 : (w == 1) ? Wc2 : (w == 2) ? Wm : Wd;
    uint32_t v = tf32_of(src[k * 256 + n]);
    if (w < 3) g_WT32[w][n * 256 + k] = v;
    else       g_Wd32[n * 256 + k] = v;
}

// ======================= kernel 1a: 4 tanh-gated projections via tf32 mma =======================
static constexpr int PBUF = 24576;   // A 8KB + B 16KB
static constexpr int SMEM_P = 2 * PBUF;  // 48KB

__global__ __launch_bounds__(256)
void projmma_kernel(const float* __restrict__ Hp, const float* __restrict__ Hq) {
    extern __shared__ char psm[];
    const uint32_t sb = smem_u32(psm);
    const int bx = blockIdx.x;
    const int gemm = bx >> 5;
    const int rr = bx & 31;
    const int mb = (rr >> 1) * 64, nb = (rr & 1) * 128;
    const float* A = (gemm == 1 || gemm == 3) ? Hp : Hq;
    const uint32_t* WT = g_WT32[gemm < 2 ? gemm : 2];
    float* C = (gemm == 0) ? g_S1 : (gemm == 1) ? g_S2 : (gemm == 2) ? g_M1 : g_M2;

    const int tid = threadIdx.x, lane = tid & 31, warp = tid >> 5;
    const int wm = warp >> 1, wn = warp & 1;

    const int a_row  = wm * 16 + (lane & 15);
    const int a_cb   = (lane >> 4) * 16;
    const int b_row2 = wn * 64 + ((lane >> 4) & 1) * 8 + (lane & 7);
    const int b_cb2  = ((lane >> 3) & 1) * 16;

    float acc[8][4];
    #pragma unroll
    for (int n = 0; n < 8; ++n)
        #pragma unroll
        for (int e = 0; e < 4; ++e) acc[n][e] = 0.f;

    auto fillA = [&](char* base, int kc) {
        #pragma unroll
        for (int t = 0; t < 2; ++t) {
            int i = tid + t * 256;
            int row = i >> 3, c = i & 7;
            float4 v = *reinterpret_cast<const float4*>(
                &A[(mb + row) * 256 + kc * 32 + c * 4]);
            uint4 u;
            u.x = tf32_of(v.x); u.y = tf32_of(v.y);
            u.z = tf32_of(v.z); u.w = tf32_of(v.w);
            *reinterpret_cast<uint4*>(base + SWZ128((uint32_t)(row * 128 + c * 16))) = u;
        }
    };
    auto fillB = [&](char* base, int kc) {
        uint32_t bB = smem_u32(base + 8192);
        #pragma unroll
        for (int t = 0; t < 4; ++t) {
            int i = tid + t * 256;
            int row = i >> 3, c = i & 7;
            CP_ASYNC16(bB + SWZ128((uint32_t)(row * 128 + c * 16)),
                       (const void*)&WT[(nb + row) * 256 + kc * 32 + c * 4]);
        }
        CP_COMMIT();
    };

    fillA(psm, 0);
    fillB(psm, 0);
    CP_WAIT0();
    __syncthreads();

    for (int kc = 0; kc < 8; ++kc) {
        char* nxt = psm + ((kc + 1) & 1) * PBUF;
        const uint32_t aA = sb + (uint32_t)(kc & 1) * PBUF;
        const uint32_t aB = aA + 8192;

        if (kc < 7) fillB(nxt, kc + 1);

        #pragma unroll
        for (int ks = 0; ks < 4; ++ks) {
            const int k0b = ks * 32;
            uint32_t a[4];
            ldm_x4(a, aA + SWZ128((uint32_t)(a_row * 128 + k0b + a_cb)));
            #pragma unroll
            for (int n2 = 0; n2 < 4; ++n2) {
                uint32_t bf[4];
                ldm_x4(bf, aB + SWZ128((uint32_t)((b_row2 + n2 * 16) * 128 + k0b + b_cb2)));
                mma_tf32(acc[2 * n2],     a, bf);
                mma_tf32(acc[2 * n2 + 1], a, bf + 2);
            }
        }

        if (kc < 7) { fillA(nxt, kc + 1); CP_WAIT0(); }
        __syncthreads();
    }

    const int r0 = mb + wm * 16 + (lane >> 2);
    #pragma unroll
    for (int n2 = 0; n2 < 4; ++n2)
        #pragma unroll
        for (int half = 0; half < 2; ++half) {
            int cb = nb + wn * 64 + n2 * 16 + half * 8 + (lane & 3) * 2;
            const float* a4 = acc[2 * n2 + half];
            C[r0 * 256 + cb]           = a4[0];
            C[r0 * 256 + cb + 1]       = a4[1];
            C[(r0 + 8) * 256 + cb]     = a4[2];
            C[(r0 + 8) * 256 + cb + 1] = a4[3];
        }
}

// ======================= kernel 1b: G = Hq @ Wb in fp32 =======================
__global__ void projb_kernel(const float* __restrict__ Hq, const float* __restrict__ Wb) {
    const int mb = blockIdx.x * 64, nb = blockIdx.y * 64;
    const int tid = threadIdx.x, ty = tid >> 4, tx = tid & 15;

    __shared__ float As[16][68];
    __shared__ float Bs[16][68];

    float acc[4][4] = {};
    for (int kt = 0; kt < 16; ++kt) {
        {
            int m = tid >> 2, k4 = (tid & 3) * 4;
            float4 v = *reinterpret_cast<const float4*>(&Hq[(mb + m) * 256 + kt * 16 + k4]);
            As[k4 + 0][m] = v.x; As[k4 + 1][m] = v.y;
            As[k4 + 2][m] = v.z; As[k4 + 3][m] = v.w;
        }
        {
            int k = tid >> 4, n4 = (tid & 15) * 4;
            float4 v = *reinterpret_cast<const float4*>(&Wb[(kt * 16 + k) * 256 + nb + n4]);
            *reinterpret_cast<float4*>(&Bs[k][n4]) = v;
        }
        __syncthreads();
        #pragma unroll
        for (int k = 0; k < 16; ++k) {
            float a[4], bv[4];
            #pragma unroll
            for (int i = 0; i < 4; ++i) a[i] = As[k][ty + 16 * i];
            #pragma unroll
            for (int j = 0; j < 4; ++j) bv[j] = Bs[k][tx + 16 * j];
            #pragma unroll
            for (int i = 0; i < 4; ++i)
                #pragma unroll
                for (int j = 0; j < 4; ++j) acc[i][j] = fmaf(a[i], bv[j], acc[i][j]);
        }
        __syncthreads();
    }
    #pragma unroll
    for (int i = 0; i < 4; ++i)
        #pragma unroll
        for (int j = 0; j < 4; ++j)
            g_G[(mb + ty + 16 * i) * 256 + nb + tx + 16 * j] = acc[i][j];
}

// ======================= kernel 2: branch d — tf32 mma, LDG-prefetch (r11 exact) =======================
static constexpr int BUFSZ   = 49152;
static constexpr int OFF_HP  = 2 * BUFSZ;
static constexpr int OFF_VD  = OFF_HP + 1024;
static constexpr int OFF_SDP = OFF_VD + 1024;
static constexpr int SMEM_D  = OFF_SDP + 1024;    // 101376

__device__ __forceinline__ void ldA_regs(float4 (&pf)[4], const float* __restrict__ hq_b,
                                         int qh, int kc, int tid) {
    #pragma unroll
    for (int t = 0; t < 4; ++t) {
        int i = tid + t * 256;
        int row = i >> 3, c = i & 7;
        pf[t] = *reinterpret_cast<const float4*>(
            &hq_b[(qh * 128 + row) * DD + kc * 32 + c * 4]);
    }
}

__device__ __forceinline__ void stA_regs(char* base, const float4 (&pf)[4],
                                         const float* hp_s, int kc, int tid) {
    #pragma unroll
    for (int t = 0; t < 4; ++t) {
        int i = tid + t * 256;
        int row = i >> 3, c = i & 7;
        int kg = kc * 32 + c * 4;
        uint4 r;
        r.x = tf32_of(pf[t].x * hp_s[kg + 0]);
        r.y = tf32_of(pf[t].y * hp_s[kg + 1]);
        r.z = tf32_of(pf[t].z * hp_s[kg + 2]);
        r.w = tf32_of(pf[t].w * hp_s[kg + 3]);
        *reinterpret_cast<uint4*>(base + SWZ128((uint32_t)(row * 128 + c * 16))) = r;
    }
}

__device__ __forceinline__ void fill_Bd(char* base, int kc, int tid) {
    uint32_t bB = smem_u32(base + 16384);
    #pragma unroll
    for (int t = 0; t < 8; ++t) {
        int i = tid + t * 256;
        int row = i >> 3, c = i & 7;
        int goff = row * DD + kc * 32 + c * 4;
        CP_ASYNC16(bB + SWZ128((uint32_t)(row * 128 + c * 16)), (const void*)&g_Wd32[goff]);
    }
}

__device__ __forceinline__ void mma_ksd(int ks, uint32_t aA, uint32_t aB,
                                        int a_row, int a_cb, int b_row, int b_cb, int wh,
                                        float (&acc)[4][8][4]) {
    const int k0b = ks * 32;
    uint32_t a[4][4];
    #pragma unroll
    for (int m = 0; m < 4; ++m) {
        uint32_t offA = SWZ128((uint32_t)((a_row + m * 16) * 128 + k0b + a_cb));
        ldm_x4(a[m], aA + offA);
    }
    #pragma unroll
    for (int n = 0; n < 8; ++n) {
        uint32_t offB = SWZ128((uint32_t)((b_row + n * 8) * 128 + k0b + b_cb));
        uint32_t bf[2];
        ldm_x2(bf, aB + offB);
        #pragma unroll
        for (int m = 0; m < 4; ++m) mma_tf32(acc[m][n], a[m], bf);
    }
}

__global__ __launch_bounds__(256, 1)
void branchd_kernel(const float* __restrict__ Hp, const float* __restrict__ Hq,
                    const float* __restrict__ vd) {
    extern __shared__ char dsm[];
    const uint32_t sb = smem_u32(dsm);
    const int p = blockIdx.x, b = blockIdx.y;
    const int tid = threadIdx.x, lane = tid & 31, warp = tid >> 5;
    const int wq = warp >> 2, wh = warp & 3;

    float* hp_s = reinterpret_cast<float*>(dsm + OFF_HP);
    float* vd_s = reinterpret_cast<float*>(dsm + OFF_VD);
    float* sdp  = reinterpret_cast<float*>(dsm + OFF_SDP);
    hp_s[tid] = Hp[(b * LL + p) * DD + tid];
    vd_s[tid] = vd[tid];
    sdp[tid] = 0.f;
    __syncthreads();

    const int a_row = wq * 64 + (lane & 15);
    const int a_cb  = (lane >> 4) * 16;
    const int b_row = wh * 64 + (lane & 7);
    const int b_cb  = ((lane >> 3) & 1) * 16;

    const float* hq_b = Hq + (b * LL) * DD;

    {
        float4 pf[4];
        ldA_regs(pf, hq_b, 0, 0, tid);
        stA_regs(dsm, pf, hp_s, 0, tid);
        fill_Bd(dsm, 0, tid);
        CP_COMMIT();
        CP_WAIT0();
        __syncthreads();
    }

    for (int qh = 0; qh < 2; ++qh) {
        float acc[4][8][4];
        #pragma unroll
        for (int m = 0; m < 4; ++m)
            #pragma unroll
            for (int n = 0; n < 8; ++n)
                #pragma unroll
                for (int e = 0; e < 4; ++e) acc[m][n][e] = 0.f;

        for (int kc = 0; kc < 8; ++kc) {
            const int t = qh * 8 + kc;
            const uint32_t aA = sb + (uint32_t)(t & 1) * BUFSZ;
            const uint32_t aB = aA + 16384;
            char* nbase = dsm + ((t + 1) & 1) * BUFSZ;

            float4 pf[4];
            if (t < 15) {
                ldA_regs(pf, hq_b, (t + 1) >> 3, (t + 1) & 7, tid);
                fill_Bd(nbase, (t + 1) & 7, tid);
                CP_COMMIT();
            }

            mma_ksd(0, aA, aB, a_row, a_cb, b_row, b_cb, wh, acc);
            mma_ksd(1, aA, aB, a_row, a_cb, b_row, b_cb, wh, acc);
            mma_ksd(2, aA, aB, a_row, a_cb, b_row, b_cb, wh, acc);

            if (t < 15) stA_regs(nbase, pf, hp_s, (t + 1) & 7, tid);

            mma_ksd(3, aA, aB, a_row, a_cb, b_row, b_cb, wh, acc);

            if (t < 15) CP_WAIT0();
            __syncthreads();
        }
        #pragma unroll
        for (int m = 0; m < 4; ++m) {
            float s0 = 0.f, s1 = 0.f;
            #pragma unroll
            for (int n = 0; n < 8; ++n) {
                int h = wh * 64 + n * 8 + (lane & 3) * 2;
                s0 = fmaf(tanh_fast(acc[m][n][0]), vd_s[h],     s0);
                s0 = fmaf(tanh_fast(acc[m][n][1]), vd_s[h + 1], s0);
                s1 = fmaf(tanh_fast(acc[m][n][2]), vd_s[h],     s1);
                s1 = fmaf(tanh_fast(acc[m][n][3]), vd_s[h + 1], s1);
            }
            s0 += __shfl_xor_sync(0xffffffffu, s0, 1);
            s0 += __shfl_xor_sync(0xffffffffu, s0, 2);
            s1 += __shfl_xor_sync(0xffffffffu, s1, 1);
            s1 += __shfl_xor_sync(0xffffffffu, s1, 2);
            if ((lane & 3) == 0) {
                int q = qh * 128 + wq * 64 + m * 16 + (lane >> 2);
                atomicAdd(&sdp[q], s0);
                atomicAdd(&sdp[q + 8], s1);
            }
        }
    }
    __syncthreads();
    g_SD[(b * LL + p) * LL + tid] = sdp[tid];
}

// ======================= kernel 3 (F1): scores c, b, m — vectorized, 16-row chunks =======================
// Warp w handles p = p0+w, p0+w+8. Lane covers h = {4*lane.., 128+4*lane..}. 4 chunks of 16 q-rows.
__global__ __launch_bounds__(256, 2)
void score_kernel(const float* __restrict__ Hp,
                  const float* __restrict__ vc, const float* __restrict__ vm) {
    __shared__ __align__(16) float s1c[2][16][256];
    __shared__ __align__(16) float m1c[2][16][256];
    __shared__ __align__(16) float gc [2][16][256];

    const int q0 = blockIdx.x * 64, p0 = blockIdx.y * 16, b = blockIdx.z;
    const int tid = threadIdx.x, lane = tid & 31, w = tid >> 5;
    const int hA = 4 * lane, hB = 128 + 4 * lane;

    const float4 vc4a = *reinterpret_cast<const float4*>(&vc[hA]);
    const float4 vc4b = *reinterpret_cast<const float4*>(&vc[hB]);
    const float4 vm4a = *reinterpret_cast<const float4*>(&vm[hA]);
    const float4 vm4b = *reinterpret_cast<const float4*>(&vm[hB]);

    float4 s2a[2], s2b[2], m2a[2], m2b[2], hpa[2], hpb[2];
    #pragma unroll
    for (int pi = 0; pi < 2; ++pi) {
        int p = p0 + w + 8 * pi;
        s2a[pi] = *reinterpret_cast<const float4*>(&g_S2[(b * LL + p) * HH + hA]);
        s2b[pi] = *reinterpret_cast<const float4*>(&g_S2[(b * LL + p) * HH + hB]);
        m2a[pi] = *reinterpret_cast<const float4*>(&g_M2[(b * LL + p) * HH + hA]);
        m2b[pi] = *reinterpret_cast<const float4*>(&g_M2[(b * LL + p) * HH + hB]);
        hpa[pi] = *reinterpret_cast<const float4*>(&Hp[(b * LL + p) * DD + hA]);
        hpb[pi] = *reinterpret_cast<const float4*>(&Hp[(b * LL + p) * DD + hB]);
    }

    // chunk = 16 q-rows of S1/M1/G (48KB): 12 cp.async per thread
    auto issue_chunk = [&](int c, int cb) {
        #pragma unroll
        for (int t = 0; t < 12; ++t) {
            int i = tid + t * 256;        // 0..3071
            int arr = i >> 10, rem = i & 1023, row = rem >> 6, c16 = rem & 63;
            int gidx = (b * LL + q0 + c * 16 + row) * HH + c16 * 4;
            const float* src;
            float* dst;
            if (arr == 0)      { src = &g_S1[gidx]; dst = &s1c[cb][row][c16 * 4]; }
            else if (arr == 1) { src = &g_M1[gidx]; dst = &m1c[cb][row][c16 * 4]; }
            else               { src = &g_G [gidx]; dst = &gc [cb][row][c16 * 4]; }
            CP_ASYNC16(smem_u32(dst), (const void*)src);
        }
        CP_COMMIT();
    };

    issue_chunk(0, 0);
    for (int c = 0; c < 4; ++c) {
        int cb = c & 1;
        if (c < 3) { issue_chunk(c + 1, (c + 1) & 1); CP_WAIT1(); }
        else       { CP_WAIT0(); }
        __syncthreads();

        #pragma unroll 2
        for (int r = 0; r < 16; ++r) {
            const float4 s1a = *reinterpret_cast<const float4*>(&s1c[cb][r][hA]);
            const float4 s1b = *reinterpret_cast<const float4*>(&s1c[cb][r][hB]);
            const float4 m1a = *reinterpret_cast<const float4*>(&m1c[cb][r][hA]);
            const float4 m1b = *reinterpret_cast<const float4*>(&m1c[cb][r][hB]);
            const float4 ga  = *reinterpret_cast<const float4*>(&gc [cb][r][hA]);
            const float4 gb  = *reinterpret_cast<const float4*>(&gc [cb][r][hB]);

            float red[6];
            #pragma unroll
            for (int pi = 0; pi < 2; ++pi) {
                float ac, am, ab;
                ac  = tanh_fast(s1a.x + s2a[pi].x) * vc4a.x;
                ac  = fmaf(tanh_fast(s1a.y + s2a[pi].y), vc4a.y, ac);
                ac  = fmaf(tanh_fast(s1a.z + s2a[pi].z), vc4a.z, ac);
                ac  = fmaf(tanh_fast(s1a.w + s2a[pi].w), vc4a.w, ac);
                ac  = fmaf(tanh_fast(s1b.x + s2b[pi].x), vc4b.x, ac);
                ac  = fmaf(tanh_fast(s1b.y + s2b[pi].y), vc4b.y, ac);
                ac  = fmaf(tanh_fast(s1b.z + s2b[pi].z), vc4b.z, ac);
                ac  = fmaf(tanh_fast(s1b.w + s2b[pi].w), vc4b.w, ac);

                am  = tanh_fast(m1a.x - m2a[pi].x) * vm4a.x;
                am  = fmaf(tanh_fast(m1a.y - m2a[pi].y), vm4a.y, am);
                am  = fmaf(tanh_fast(m1a.z - m2a[pi].z), vm4a.z, am);
                am  = fmaf(tanh_fast(m1a.w - m2a[pi].w), vm4a.w, am);
                am  = fmaf(tanh_fast(m1b.x - m2b[pi].x), vm4b.x, am);
                am  = fmaf(tanh_fast(m1b.y - m2b[pi].y), vm4b.y, am);
                am  = fmaf(tanh_fast(m1b.z - m2b[pi].z), vm4b.z, am);
                am  = fmaf(tanh_fast(m1b.w - m2b[pi].w), vm4b.w, am);

                ab  = hpa[pi].x * ga.x;
                ab  = fmaf(hpa[pi].y, ga.y, ab);
                ab  = fmaf(hpa[pi].z, ga.z, ab);
                ab  = fmaf(hpa[pi].w, ga.w, ab);
                ab  = fmaf(hpb[pi].x, gb.x, ab);
                ab  = fmaf(hpb[pi].y, gb.y, ab);
                ab  = fmaf(hpb[pi].z, gb.z, ab);
                ab  = fmaf(hpb[pi].w, gb.w, ab);

                red[3 * pi + 0] = ac;
                red[3 * pi + 1] = ab;
                red[3 * pi + 2] = am;
            }
            #pragma unroll
            for (int o = 16; o; o >>= 1)
                #pragma unroll
                for (int j = 0; j < 6; ++j)
                    red[j] += __shfl_xor_sync(0xffffffffu, red[j], o);
            if (lane == 0) {
                int q = q0 + c * 16 + r;
                #pragma unroll
                for (int pi = 0; pi < 2; ++pi) {
                    int p = p0 + w + 8 * pi;
                    int idx = (b * LL + p) * LL + q;
                    g_SC[idx] = red[3 * pi + 0];
                    g_SB[idx] = red[3 * pi + 1];
                    g_SM[idx] = red[3 * pi + 2];
                }
            }
        }
        __syncthreads();
    }
}

// ======================= kernel 4 (F2): softmax + attend (r8 exact) =======================
__global__ __launch_bounds__(256)
void attend_kernel(const float* __restrict__ Hq, float* __restrict__ out) {
    __shared__ float wsm[256][36];

    const int p0 = blockIdx.x * 8, b = blockIdx.y;
    const int tid = threadIdx.x, lane = tid & 31, w = tid >> 5;

    const float* srcs[4] = {g_SC, g_SB, g_SD, g_SM};
    #pragma unroll
    for (int t = 0; t < 32; ++t) {
        int i = tid + t * 256;
        int p = i >> 10, br = (i >> 8) & 3, q = i & 255;
        wsm[q][p * 4 + br] = srcs[br][(b * LL + p0 + p) * LL + q];
    }
    __syncthreads();

    #pragma unroll
    for (int s = 0; s < 4; ++s) {
        int slot = w + 8 * s;
        float v[8];
        #pragma unroll
        for (int i = 0; i < 8; ++i) v[i] = wsm[lane + 32 * i][slot];
        float mx = v[0];
        #pragma unroll
        for (int i = 1; i < 8; ++i) mx = fmaxf(mx, v[i]);
        #pragma unroll
        for (int o = 16; o; o >>= 1) mx = fmaxf(mx, __shfl_xor_sync(0xffffffffu, mx, o));
        float sum = 0.f;
        #pragma unroll
        for (int i = 0; i < 8; ++i) { v[i] = __expf(v[i] - mx); sum += v[i]; }
        #pragma unroll
        for (int o = 16; o; o >>= 1) sum += __shfl_xor_sync(0xffffffffu, sum, o);
        float inv = 1.0f / sum;
        #pragma unroll
        for (int i = 0; i < 8; ++i) wsm[lane + 32 * i][slot] = v[i] * inv;
    }
    __syncthreads();

    float acc[32];
    #pragma unroll
    for (int s = 0; s < 32; ++s) acc[s] = 0.f;
    const float* hqb = &Hq[(b * LL) * DD + tid];
    #pragma unroll 4
    for (int q = 0; q < LL; ++q) {
        float hq = hqb[q * DD];
        #pragma unroll
        for (int j = 0; j < 8; ++j) {
            float4 wv = *reinterpret_cast<const float4*>(&wsm[q][j * 4]);
            acc[j * 4 + 0] = fmaf(wv.x, hq, acc[j * 4 + 0]);
            acc[j * 4 + 1] = fmaf(wv.y, hq, acc[j * 4 + 1]);
            acc[j * 4 + 2] = fmaf(wv.z, hq, acc[j * 4 + 2]);
            acc[j * 4 + 3] = fmaf(wv.w, hq, acc[j * 4 + 3]);
        }
    }
    const int BR = BB * LL * DD;
    #pragma unroll
    for (int p = 0; p < 8; ++p)
        #pragma unroll
        for (int br = 0; br < 4; ++br)
            out[br * BR + (b * LL + p0 + p) * DD + tid] = acc[p * 4 + br];
}

// ======================= launch =======================
extern "C" void kernel_launch(void* const* d_in, const int* in_sizes, int n_in,
                              void* d_out, int out_size) {
    (void)in_sizes; (void)n_in; (void)out_size;
    const float* Hp  = (const float*)d_in[0];
    const float* Hq  = (const float*)d_in[1];
    const float* Wc1 = (const float*)d_in[2];
    const float* Wc2 = (const float*)d_in[3];
    const float* vc  = (const float*)d_in[4];
    const float* Wb  = (const float*)d_in[5];
    const float* Wd  = (const float*)d_in[6];
    const float* vd  = (const float*)d_in[7];
    const float* Wm  = (const float*)d_in[8];
    const float* vm  = (const float*)d_in[9];
    float* out = (float*)d_out;

    cudaFuncSetAttribute(branchd_kernel,
                         cudaFuncAttributeMaxDynamicSharedMemorySize, SMEM_D);
    cudaFuncSetAttribute(projmma_kernel,
                         cudaFuncAttributeMaxDynamicSharedMemorySize, SMEM_P);

    dim3 gw(256, 4);
    prep_w_kernel<<<gw, 256>>>(Wc1, Wc2, Wm, Wd);

    projmma_kernel<<<128, 256, SMEM_P>>>(Hp, Hq);

    dim3 gb(16, 4);
    projb_kernel<<<gb, 256>>>(Hq, Wb);

    dim3 gd(LL, BB);
    branchd_kernel<<<gd, 256, SMEM_D>>>(Hp, Hq, vd);

    dim3 gs(4, 16, 4);
    score_kernel<<<gs, 256>>>(Hp, vc, vm);

    dim3 ga(32, 4);
    attend_kernel<<<ga, 256>>>(Hq, out);
}